// round 12
// baseline (speedup 1.0000x reference)
#include <cuda_runtime.h>
#include <cuda_fp16.h>
#include <cstdint>
#include <cstddef>

// ---------------------------------------------------------------------------
// LSTM cell, B=65536, I=H=256. Baseline-PTX path (no tcgen05 on this
// harness's ptxas target): cp.async + ldmatrix + mma.sync.m16n8k16 (f16 acc;
// measured same HMMA rate as f32 acc on sm_103, half the registers).
//
// Pass 1: [x|h] -> fp16 scratch (B x 512), [Wi|Wh] -> fp16 (1024 x 512).
// Pass 2: persistent GEMM+LSTM. 296 CTAs (2/SM), each loops over ~14 work
//         units (m_tile 128 rows x jslice 32 h-cols; N=128 = 4 gates x 32).
//         3-stage cp.async pipeline flows continuously ACROSS units (chunk
//         g prefetches g+2, possibly of the next unit) -> no fill/drain, no
//         wave transitions. Epilogue: warp-pair f16x2 register exchange via
//         8KB smem + named barriers (bar.sync id,64) -> no full-CTA syncs.
// Output: d_out[0 : B*H] = h_new, d_out[B*H : 2*B*H] = c_new.
// ---------------------------------------------------------------------------

#define BATCH   65536
#define HID     256
#define KDIM    512
#define M_TILE  128
#define KC      64            // halves per K chunk = 128 bytes per row
#define NCHUNK  8             // 512 / 64
#define NSTG    3
#define STAGE_A 16384         // 128 rows * 128B
#define STAGE_B 16384         // 128 rows * 128B
#define STAGE_BYTES 32768
#define XBUF_OFF (NSTG * STAGE_BYTES)        // 98304
#define DYN_SMEM (XBUF_OFF + 8192)           // 104KB -> 2 CTAs/SM
#define NUNITS  4096          // 512 m-tiles x 8 jslices
#define GRID    296           // 2 CTAs x 148 SMs, persistent

// fp16 scratch (module-static device memory; no runtime allocation)
__device__ __half xh16g[(size_t)BATCH * KDIM];   // 64 MB
__device__ __half w16g[1024 * KDIM];             // 1 MB

// ---------------- helpers ----------------

__device__ __forceinline__ uint32_t swz(uint32_t o) {
    return o ^ ((o >> 3) & 0x70);          // xor bits[4:6] with bits[7:9]
}

#define CP_ASYNC16(dst, src) \
    asm volatile("cp.async.cg.shared.global [%0], [%1], 16;" \
                 :: "r"(dst), "l"(src) : "memory")

#define CP_COMMIT() asm volatile("cp.async.commit_group;" ::: "memory")

#define LDSM4(R, addr) \
    asm volatile("ldmatrix.sync.aligned.m8n8.x4.shared.b16 {%0,%1,%2,%3}, [%4];" \
                 : "=r"((R)[0]), "=r"((R)[1]), "=r"((R)[2]), "=r"((R)[3]) \
                 : "r"(addr))

#define MMA16816H_Z(d, a, b0, b1) \
    asm volatile("mma.sync.aligned.m16n8k16.row.col.f16.f16.f16.f16 " \
                 "{%0,%1},{%2,%3,%4,%5},{%6,%7},{%8,%8};" \
                 : "=r"((d)[0]), "=r"((d)[1]) \
                 : "r"((a)[0]), "r"((a)[1]), "r"((a)[2]), "r"((a)[3]), \
                   "r"(b0), "r"(b1), "r"(0u))

#define MMA16816H(d, a, b0, b1) \
    asm volatile("mma.sync.aligned.m16n8k16.row.col.f16.f16.f16.f16 " \
                 "{%0,%1},{%2,%3,%4,%5},{%6,%7},{%0,%1};" \
                 : "+r"((d)[0]), "+r"((d)[1]) \
                 : "r"((a)[0]), "r"((a)[1]), "r"((a)[2]), "r"((a)[3]), \
                   "r"(b0), "r"(b1))

#define HADD2(d, a) \
    asm volatile("add.rn.f16x2 %0, %0, %1;" : "+r"(d) : "r"(a))

#define PAIR_BAR(id) \
    asm volatile("bar.sync %0, 64;" :: "r"(id) : "memory")

__device__ __forceinline__ float sigf(float x) {
    return __fdividef(1.0f, 1.0f + __expf(-x));
}
__device__ __forceinline__ float tanhf_fast(float x) {
    return 1.0f - __fdividef(2.0f, 1.0f + __expf(2.0f * x));
}

// ---------------- pass 1: fp32 -> fp16 concat convert ----------------

__global__ void __launch_bounds__(256) conv_all_kernel(const float* __restrict__ x,
                                                       const float* __restrict__ h,
                                                       const float* __restrict__ Wi,
                                                       const float* __restrict__ Wh)
{
    size_t i = ((size_t)blockIdx.x * blockDim.x + threadIdx.x) * 8;
    if (i >= (size_t)(BATCH + 1024) * KDIM) return;
    int r = (int)(i >> 9);
    int k = (int)(i & 511);
    const float* A;
    const float* Bm;
    __half* dst;
    size_t row;
    if (r < BATCH) { A = x;  Bm = h;  dst = xh16g; row = (size_t)r; }
    else           { A = Wi; Bm = Wh; dst = w16g;  row = (size_t)(r - BATCH); }
    const float* s = (k < 256) ? (A + row * 256 + k) : (Bm + row * 256 + (k - 256));
    float4 f0 = ((const float4*)s)[0];
    float4 f1 = ((const float4*)s)[1];
    __half2 h0 = __floats2half2_rn(f0.x, f0.y);
    __half2 h1 = __floats2half2_rn(f0.z, f0.w);
    __half2 h2 = __floats2half2_rn(f1.x, f1.y);
    __half2 h3 = __floats2half2_rn(f1.z, f1.w);
    uint4 v;
    v.x = *(uint32_t*)&h0; v.y = *(uint32_t*)&h1;
    v.z = *(uint32_t*)&h2; v.w = *(uint32_t*)&h3;
    *(uint4*)(dst + row * KDIM + k) = v;
}

// ---------------- pass 2: persistent GEMM + LSTM ----------------
// B tile rows: tile row r -> gate g = r>>5, jj = r&31, weight row g*256+jbase+jj

__device__ __forceinline__ void issue_stage(uint32_t smb, int stage, int kc,
                                            int tid, int mrow, int jbase)
{
    const uint32_t abase = smb + stage * STAGE_BYTES;
    const uint32_t bbase = abase + STAGE_A;
    #pragma unroll
    for (int j = 0; j < 8; ++j) {
        const int slot = tid + j * 256;          // 0..2047
        if (slot < 1024) {                       // A: 128 rows x 8 segs of 16B
            const int row = slot >> 3, seg = slot & 7;
            const uint32_t d = abase + swz(row * 128 + seg * 16);
            const __half* src = xh16g + ((size_t)(mrow + row) << 9) + kc * KC + seg * 8;
            CP_ASYNC16(d, src);
        } else {                                 // B: 128 rows x 8 segs
            const int t = slot - 1024;
            const int row = t >> 3, seg = t & 7;
            const int wrow = ((row >> 5) << 8) + jbase + (row & 31);
            const uint32_t d = bbase + swz(row * 128 + seg * 16);
            const __half* src = w16g + ((size_t)wrow << 9) + kc * KC + seg * 8;
            CP_ASYNC16(d, src);
        }
    }
}

// Epilogue body for one warp-pair half. WN = this warp's column role.
// wn=0 owns gates i (nt 0..3) / f (nt 4..7); wn=1 owns g / o.
// wn=0 computes row-half mt=0, wn=1 computes mt=1; each writes its OTHER
// mt-half so the peer (same lane!) can read it.
#define EPI_BODY(WN)                                                          \
    _Pragma("unroll")                                                         \
    for (int t = 0; t < 2; ++t) {                                             \
        PAIR_BAR(1 + wm);                                                     \
        _Pragma("unroll")                                                     \
        for (int ss = 0; ss < 2; ++ss)                                        \
            _Pragma("unroll")                                                 \
            for (int rg = 0; rg < 2; ++rg) {                                  \
                xb[ss * 2 + rg]     = hmast[1 - WN][2 * t + ss][rg];          \
                xb[4 + ss * 2 + rg] = hmast[1 - WN][4 + 2 * t + ss][rg];      \
            }                                                                 \
        PAIR_BAR(1 + wm);                                                     \
        _Pragma("unroll")                                                     \
        for (int ss = 0; ss < 2; ++ss)                                        \
            _Pragma("unroll")                                                 \
            for (int rg = 0; rg < 2; ++rg) {                                  \
                uint32_t iu, fu, gu, ou;                                      \
                if (WN == 0) {                                                \
                    iu = hmast[0][2 * t + ss][rg];                            \
                    fu = hmast[0][4 + 2 * t + ss][rg];                        \
                    gu = pb[ss * 2 + rg];  ou = pb[4 + ss * 2 + rg];          \
                } else {                                                      \
                    gu = hmast[1][2 * t + ss][rg];                            \
                    ou = hmast[1][4 + 2 * t + ss][rg];                        \
                    iu = pb[ss * 2 + rg];  fu = pb[4 + ss * 2 + rg];          \
                }                                                             \
                const int jp = 16 * t + 8 * ss + q2;                          \
                const int R  = wm * 32 + WN * 16 + rl + 8 * rg;               \
                float2 gi = __half22float2(*(const __half2*)&iu);             \
                float2 gf = __half22float2(*(const __half2*)&fu);             \
                float2 gg = __half22float2(*(const __half2*)&gu);             \
                float2 go = __half22float2(*(const __half2*)&ou);             \
                gi.x += sbias[jp];      gi.y += sbias[jp + 1];                \
                gf.x += sbias[32 + jp]; gf.y += sbias[33 + jp];               \
                gg.x += sbias[64 + jp]; gg.y += sbias[65 + jp];               \
                go.x += sbias[96 + jp]; go.y += sbias[97 + jp];               \
                const size_t gp = (size_t)(mrow + R) * HID + jbase + jp;      \
                const float2 cv = *(const float2*)(c_in + gp);                \
                float2 cc, hn;                                                \
                cc.x = sigf(gf.x) * cv.x + sigf(gi.x) * tanhf_fast(gg.x);     \
                cc.y = sigf(gf.y) * cv.y + sigf(gi.y) * tanhf_fast(gg.y);     \
                hn.x = sigf(go.x) * tanhf_fast(cc.x);                         \
                hn.y = sigf(go.y) * tanhf_fast(cc.y);                         \
                *(float2*)(c_out + gp) = cc;                                  \
                *(float2*)(h_out + gp) = hn;                                  \
            }                                                                 \
    }

extern "C" __global__ void __launch_bounds__(256, 2)
lstm_gemm_kernel(const float* __restrict__ c_in,
                 const float* __restrict__ bi,
                 const float* __restrict__ bh,
                 float* __restrict__ h_out,
                 float* __restrict__ c_out)
{
    extern __shared__ __align__(1024) char dynsmem[];
    __shared__ float sbias[128];

    const int tid  = threadIdx.x;
    const int lane = tid & 31;
    const int wid  = tid >> 5;
    const int wm   = wid >> 1;           // warp row 0..3 (32 m-rows each)
    const int wn   = wid & 1;            // warp col 0..1 (64 tile-cols each)
    const int q2   = 2 * (lane & 3);
    const int rl   = lane >> 2;

    const uint32_t smb = (uint32_t)__cvta_generic_to_shared(dynsmem);
    uint32_t* xbuf = (uint32_t*)(dynsmem + XBUF_OFF);
    uint32_t* xb = xbuf + ((wm * 2 + wn) * 32 + lane) * 8;        // my slot
    uint32_t* pb = xbuf + ((wm * 2 + (1 - wn)) * 32 + lane) * 8;  // peer slot

    // master accumulators: f16x2, [mt][nt][reg]
    uint32_t hmast[2][8][2];
    #pragma unroll
    for (int mt = 0; mt < 2; ++mt)
        #pragma unroll
        for (int nt = 0; nt < 8; ++nt) {
            hmast[mt][nt][0] = 0u;
            hmast[mt][nt][1] = 0u;
        }

    // ldmatrix per-lane offsets (within a 128B-wide swizzled row layout)
    const int a_row0 = wm * 32 + (lane & 15);
    const int a_koff = (lane >> 4) * 16;
    const int b_rowc = wn * 64 + ((lane >> 4) << 3) + (lane & 7);
    const int b_koff = ((lane >> 3) & 1) * 16;

    // persistent unit loop: unit u -> m_tile = u>>3 (128 rows), jslice = u&7
    int u = (int)blockIdx.x;
    int mrow  = (u >> 3) * M_TILE;
    int jbase = (u & 7) * 32;

    // prologue: prefetch chunks 0,1 of first unit
    issue_stage(smb, 0, 0, tid, mrow, jbase); CP_COMMIT();
    issue_stage(smb, 1, 1, tid, mrow, jbase); CP_COMMIT();
    int stage = 0;

    for (; u < NUNITS; u += GRID) {
        mrow  = (u >> 3) * M_TILE;
        jbase = (u & 7) * 32;
        const int u2     = u + GRID;
        const int mrow2  = (u2 >> 3) * M_TILE;
        const int jbase2 = (u2 & 7) * 32;

        for (int k = 0; k < NCHUNK; ++k) {
            asm volatile("cp.async.wait_group 1;" ::: "memory");
            __syncthreads();

            if (k == 0 && tid < 128) {       // this unit's bias sums
                const int g = tid >> 5, jj = tid & 31;
                const int col = g * 256 + jbase + jj;
                sbias[tid] = bi[col] + bh[col];
            }

            int ps = stage + 2; if (ps >= NSTG) ps -= NSTG;
            if (k < NCHUNK - 2)
                issue_stage(smb, ps, k + 2, tid, mrow, jbase);
            else if (u2 < NUNITS)
                issue_stage(smb, ps, k - 6, tid, mrow2, jbase2);
            CP_COMMIT();

            const uint32_t abase = smb + stage * STAGE_BYTES;
            const uint32_t bbase = abase + STAGE_A;

            uint32_t hchk[2][8][2];          // per-chunk f16 partial sums

            #pragma unroll
            for (int kt = 0; kt < 4; ++kt) {
                uint32_t aF[2][4];
                #pragma unroll
                for (int mt = 0; mt < 2; ++mt) {
                    const uint32_t o = (uint32_t)((a_row0 + mt * 16) * 128 + kt * 32 + a_koff);
                    LDSM4(aF[mt], abase + swz(o));
                }
                uint32_t bF[4][4];
                #pragma unroll
                for (int nt2 = 0; nt2 < 4; ++nt2) {
                    const uint32_t o = (uint32_t)((b_rowc + nt2 * 16) * 128 + kt * 32 + b_koff);
                    LDSM4(bF[nt2], bbase + swz(o));
                }
                if (kt == 0) {
                    #pragma unroll
                    for (int mt = 0; mt < 2; ++mt)
                        #pragma unroll
                        for (int nt = 0; nt < 8; ++nt)
                            MMA16816H_Z(hchk[mt][nt], aF[mt],
                                        bF[nt >> 1][(nt & 1) * 2], bF[nt >> 1][(nt & 1) * 2 + 1]);
                } else {
                    #pragma unroll
                    for (int mt = 0; mt < 2; ++mt)
                        #pragma unroll
                        for (int nt = 0; nt < 8; ++nt)
                            MMA16816H(hchk[mt][nt], aF[mt],
                                      bF[nt >> 1][(nt & 1) * 2], bF[nt >> 1][(nt & 1) * 2 + 1]);
                }
            }

            #pragma unroll
            for (int mt = 0; mt < 2; ++mt)
                #pragma unroll
                for (int nt = 0; nt < 8; ++nt) {
                    HADD2(hmast[mt][nt][0], hchk[mt][nt][0]);
                    HADD2(hmast[mt][nt][1], hchk[mt][nt][1]);
                }

            if (++stage == NSTG) stage = 0;
        }

        // ---- epilogue: warp-pair exchange, named barriers only ----
        if (wn == 0) { EPI_BODY(0) } else { EPI_BODY(1) }

        // reset masters for next unit
        #pragma unroll
        for (int mt = 0; mt < 2; ++mt)
            #pragma unroll
            for (int nt = 0; nt < 8; ++nt) {
                hmast[mt][nt][0] = 0u;
                hmast[mt][nt][1] = 0u;
            }
    }
}

// ---------------- host launcher ----------------

extern "C" void kernel_launch(void* const* d_in, const int* in_sizes, int n_in,
                              void* d_out, int out_size)
{
    (void)in_sizes; (void)n_in; (void)out_size;
    const float* x  = (const float*)d_in[0];
    const float* h  = (const float*)d_in[1];
    const float* c  = (const float*)d_in[2];
    const float* Wi = (const float*)d_in[3];
    const float* Wh = (const float*)d_in[4];
    const float* bi = (const float*)d_in[5];
    const float* bh = (const float*)d_in[6];
    float* hout = (float*)d_out;
    float* cout = hout + (size_t)BATCH * HID;

    // pass 1: single conversion kernel (xh + weights)
    {
        const size_t n = (size_t)(BATCH + 1024) * KDIM / 8;
        conv_all_kernel<<<(unsigned)((n + 255) / 256), 256>>>(x, h, Wi, Wh);
    }

    // pass 2: persistent GEMM + LSTM, one wave of 296 CTAs (2/SM)
    cudaFuncSetAttribute(lstm_gemm_kernel,
                         cudaFuncAttributeMaxDynamicSharedMemorySize, DYN_SMEM);
    lstm_gemm_kernel<<<GRID, 256, DYN_SMEM>>>(c, bi, bh, hout, cout);
}

// round 13
// speedup vs baseline: 1.0821x; 1.0821x over previous
#include <cuda_runtime.h>
#include <cuda_fp16.h>
#include <cstdint>
#include <cstddef>

// ---------------------------------------------------------------------------
// LSTM cell, B=65536, I=H=256. Baseline-PTX path (no tcgen05 on this
// harness's ptxas target): cp.async + ldmatrix + mma.sync.m16n8k16.f16 acc.
//
// Pass 1: [x|h] -> fp16 scratch (B x 512), [Wi|Wh] -> fp16 (1024 x 512).
// Pass 2: gates = XH @ W^T. CTA tile M=128 x N=256 (ALL 4 gates x 64 h-cols),
//         256 threads, 2x4 warp grid of 64x64 tiles (warp-col == gate).
//         LDSM:HMMA = 1:4 (vs 1:2.67 before) -> smem crossbar pressure -33%.
//         Direct f16 accumulation (no chunk fold) keeps regs <= 128 ->
//         2 CTAs/SM. 2-stage cp.async pipeline (96KB). Fused LSTM epilogue
//         via f16x2 smem staging. Non-persistent grid (2048 CTAs).
// Output: d_out[0 : B*H] = h_new, d_out[B*H : 2*B*H] = c_new.
// ---------------------------------------------------------------------------

#define BATCH   65536
#define HID     256
#define KDIM    512
#define M_TILE  128
#define KC      64            // halves per K chunk = 128 bytes per row
#define NCHUNK  8             // 512 / 64
#define NSTG    2
#define STAGE_A 16384         // 128 rows * 128B
#define STAGE_B 32768         // 256 rows * 128B
#define STAGE_BYTES 49152
#define DYN_SMEM (NSTG * STAGE_BYTES)   // 98304 -> 2 CTAs/SM
#define SGS     132           // half2 stride for epilogue staging (128 + pad)

// fp16 scratch (module-static device memory; no runtime allocation)
__device__ __half xh16g[(size_t)BATCH * KDIM];   // 64 MB
__device__ __half w16g[1024 * KDIM];             // 1 MB

// ---------------- helpers ----------------

__device__ __forceinline__ uint32_t swz(uint32_t o) {
    return o ^ ((o >> 3) & 0x70);          // xor bits[4:6] with bits[7:9]
}

#define CP_ASYNC16(dst, src) \
    asm volatile("cp.async.cg.shared.global [%0], [%1], 16;" \
                 :: "r"(dst), "l"(src) : "memory")

#define CP_COMMIT() asm volatile("cp.async.commit_group;" ::: "memory")

#define LDSM4(R, addr) \
    asm volatile("ldmatrix.sync.aligned.m8n8.x4.shared.b16 {%0,%1,%2,%3}, [%4];" \
                 : "=r"((R)[0]), "=r"((R)[1]), "=r"((R)[2]), "=r"((R)[3]) \
                 : "r"(addr))

// fp16-accumulate MMA, chained (C = D). Internal dot product fp32, one
// rounding per instruction.
#define MMA16816H(d, a, b0, b1) \
    asm volatile("mma.sync.aligned.m16n8k16.row.col.f16.f16.f16.f16 " \
                 "{%0,%1},{%2,%3,%4,%5},{%6,%7},{%0,%1};" \
                 : "+r"((d)[0]), "+r"((d)[1]) \
                 : "r"((a)[0]), "r"((a)[1]), "r"((a)[2]), "r"((a)[3]), \
                   "r"(b0), "r"(b1))

__device__ __forceinline__ float sigf(float x) {
    return __fdividef(1.0f, 1.0f + __expf(-x));
}
__device__ __forceinline__ float tanhf_fast(float x) {
    return 1.0f - __fdividef(2.0f, 1.0f + __expf(2.0f * x));
}

// ---------------- pass 1: fp32 -> fp16 concat convert ----------------
// rows [0, BATCH):            xh16g[r*512+k] = k<256 ? x[r,k] : h[r,k-256]
// rows [BATCH, BATCH+1024):   w16g [r*512+k] = k<256 ? Wi[r,k] : Wh[r,k-256]

__global__ void __launch_bounds__(256) conv_all_kernel(const float* __restrict__ x,
                                                       const float* __restrict__ h,
                                                       const float* __restrict__ Wi,
                                                       const float* __restrict__ Wh)
{
    size_t i = ((size_t)blockIdx.x * blockDim.x + threadIdx.x) * 8;
    if (i >= (size_t)(BATCH + 1024) * KDIM) return;
    int r = (int)(i >> 9);
    int k = (int)(i & 511);
    const float* A;
    const float* Bm;
    __half* dst;
    size_t row;
    if (r < BATCH) { A = x;  Bm = h;  dst = xh16g; row = (size_t)r; }
    else           { A = Wi; Bm = Wh; dst = w16g;  row = (size_t)(r - BATCH); }
    const float* s = (k < 256) ? (A + row * 256 + k) : (Bm + row * 256 + (k - 256));
    float4 f0 = ((const float4*)s)[0];
    float4 f1 = ((const float4*)s)[1];
    __half2 h0 = __floats2half2_rn(f0.x, f0.y);
    __half2 h1 = __floats2half2_rn(f0.z, f0.w);
    __half2 h2 = __floats2half2_rn(f1.x, f1.y);
    __half2 h3 = __floats2half2_rn(f1.z, f1.w);
    uint4 v;
    v.x = *(uint32_t*)&h0; v.y = *(uint32_t*)&h1;
    v.z = *(uint32_t*)&h2; v.w = *(uint32_t*)&h3;
    *(uint4*)(dst + row * KDIM + k) = v;
}

// ---------------- pass 2: GEMM + LSTM ----------------
// B tile rows: tile row r (0..255) -> gate g = r>>6, jj = r&63,
//              weight row g*256 + jbase + jj.

__device__ __forceinline__ void issue_stage(uint32_t smb, int stage, int kc,
                                            int tid, int mrow, int jbase)
{
    const uint32_t abase = smb + stage * STAGE_BYTES;
    const uint32_t bbase = abase + STAGE_A;
    #pragma unroll
    for (int j = 0; j < 12; ++j) {
        const int slot = tid + j * 256;          // 0..3071
        if (slot < 1024) {                       // A: 128 rows x 8 segs of 16B
            const int row = slot >> 3, seg = slot & 7;
            const uint32_t d = abase + swz(row * 128 + seg * 16);
            const __half* src = xh16g + ((size_t)(mrow + row) << 9) + kc * KC + seg * 8;
            CP_ASYNC16(d, src);
        } else {                                 // B: 256 rows x 8 segs
            const int t = slot - 1024;
            const int row = t >> 3, seg = t & 7;
            const int wrow = ((row >> 6) << 8) + jbase + (row & 63);
            const uint32_t d = bbase + swz(row * 128 + seg * 16);
            const __half* src = w16g + ((size_t)wrow << 9) + kc * KC + seg * 8;
            CP_ASYNC16(d, src);
        }
    }
}

extern "C" __global__ void __launch_bounds__(256, 2)
lstm_gemm_kernel(const float* __restrict__ c_in,
                 const float* __restrict__ bi,
                 const float* __restrict__ bh,
                 float* __restrict__ h_out,
                 float* __restrict__ c_out)
{
    extern __shared__ __align__(1024) char dynsmem[];
    __shared__ float sbias[256];

    const int tid  = threadIdx.x;
    const int lane = tid & 31;
    const int wid  = tid >> 5;
    const int wm   = wid >> 2;           // warp row 0..1 (64 m-rows each)
    const int wn   = wid & 3;            // warp col 0..3 == gate (64 cols each)

    const int m_tile = (int)(blockIdx.x >> 2);
    const int jslice = (int)(blockIdx.x & 3);
    const int mrow   = m_tile * M_TILE;
    const int jbase  = jslice * 64;

    const uint32_t smb = (uint32_t)__cvta_generic_to_shared(dynsmem);

    // bias sums for tile cols tc = g*64 + jj  ->  actual col g*256+jbase+jj
    if (tid < 256) {
        const int g = tid >> 6, jj = tid & 63;
        sbias[tid] = bi[g * 256 + jbase + jj] + bh[g * 256 + jbase + jj];
    }

    // f16x2 master accumulators, direct accumulation across all 32 MMAs.
    // hmast[mt][nt]: rows wm*64+mt*16 (+8 for reg1), cols wn*64+nt*8.
    uint32_t hmast[4][8][2];
    #pragma unroll
    for (int mt = 0; mt < 4; ++mt)
        #pragma unroll
        for (int nt = 0; nt < 8; ++nt) {
            hmast[mt][nt][0] = 0u;
            hmast[mt][nt][1] = 0u;
        }

    // ldmatrix per-lane offsets
    const int a_row0 = wm * 64 + (lane & 15);
    const int a_koff = (lane >> 4) * 16;
    const int b_rowc = wn * 64 + ((lane >> 4) << 3) + (lane & 7);
    const int b_koff = ((lane >> 3) & 1) * 16;

    // prologue: chunk 0 -> stage 0
    issue_stage(smb, 0, 0, tid, mrow, jbase);
    CP_COMMIT();

    for (int k = 0; k < NCHUNK; ++k) {
        asm volatile("cp.async.wait_group 0;" ::: "memory");
        __syncthreads();   // chunk k ready; all warps done with chunk k-1

        if (k + 1 < NCHUNK) {
            issue_stage(smb, (k + 1) & 1, k + 1, tid, mrow, jbase);
            CP_COMMIT();   // overlaps with compute of chunk k below
        }

        const uint32_t abase = smb + (k & 1) * STAGE_BYTES;
        const uint32_t bbase = abase + STAGE_A;

        #pragma unroll
        for (int kt = 0; kt < 4; ++kt) {
            uint32_t aF[4][4];
            #pragma unroll
            for (int mt = 0; mt < 4; ++mt) {
                const uint32_t o = (uint32_t)((a_row0 + mt * 16) * 128 + kt * 32 + a_koff);
                LDSM4(aF[mt], abase + swz(o));
            }
            uint32_t bF[4][4];
            #pragma unroll
            for (int nt2 = 0; nt2 < 4; ++nt2) {
                const uint32_t o = (uint32_t)((b_rowc + nt2 * 16) * 128 + kt * 32 + b_koff);
                LDSM4(bF[nt2], bbase + swz(o));
            }
            #pragma unroll
            for (int mt = 0; mt < 4; ++mt)
                #pragma unroll
                for (int nt = 0; nt < 8; ++nt)
                    MMA16816H(hmast[mt][nt], aF[mt],
                              bF[nt >> 1][(nt & 1) * 2], bF[nt >> 1][(nt & 1) * 2 + 1]);
        }
    }
    __syncthreads();   // pipeline smem -> epilogue staging reuse

    // stage gates as f16x2: sg[r * SGS + hc], hc = tc/2 = g*32 + jj/2
    uint32_t* sg = (uint32_t*)dynsmem;
    {
        const int rl = lane >> 2;            // row within 8-row group
        const int hc0 = wn * 32 + (lane & 3);
        #pragma unroll
        for (int mt = 0; mt < 4; ++mt)
            #pragma unroll
            for (int nt = 0; nt < 8; ++nt) {
                const int r = wm * 64 + mt * 16 + rl;
                const int hc = hc0 + nt * 4;
                sg[r * SGS + hc]       = hmast[mt][nt][0];
                sg[(r + 8) * SGS + hc] = hmast[mt][nt][1];
            }
    }
    __syncthreads();

    // fused LSTM elementwise: 128 rows x 32 half2-cols, float2 I/O
    const float2* sb2 = (const float2*)sbias;
    #pragma unroll 4
    for (int it = 0; it < 16; ++it) {
        const int idx = it * 256 + tid;
        const int r  = idx >> 5;
        const int j2 = idx & 31;             // half2 col within the 64-col slice
        float2 gi = __half22float2(*(const __half2*)&sg[r * SGS +      j2]);
        float2 gf = __half22float2(*(const __half2*)&sg[r * SGS + 32 + j2]);
        float2 gg = __half22float2(*(const __half2*)&sg[r * SGS + 64 + j2]);
        float2 go = __half22float2(*(const __half2*)&sg[r * SGS + 96 + j2]);
        const float2 b0 = sb2[     j2], b1 = sb2[32 + j2];
        const float2 b2 = sb2[64 + j2], b3 = sb2[96 + j2];
        gi.x += b0.x; gi.y += b0.y;
        gf.x += b1.x; gf.y += b1.y;
        gg.x += b2.x; gg.y += b2.y;
        go.x += b3.x; go.y += b3.y;
        const size_t gp = (size_t)(mrow + r) * HID + jbase + 2 * j2;
        const float2 cv = *(const float2*)(c_in + gp);
        float2 cc, hn;
        cc.x = sigf(gf.x) * cv.x + sigf(gi.x) * tanhf_fast(gg.x);
        cc.y = sigf(gf.y) * cv.y + sigf(gi.y) * tanhf_fast(gg.y);
        hn.x = sigf(go.x) * tanhf_fast(cc.x);
        hn.y = sigf(go.y) * tanhf_fast(cc.y);
        *(float2*)(c_out + gp) = cc;
        *(float2*)(h_out + gp) = hn;
    }
}

// ---------------- host launcher ----------------

extern "C" void kernel_launch(void* const* d_in, const int* in_sizes, int n_in,
                              void* d_out, int out_size)
{
    (void)in_sizes; (void)n_in; (void)out_size;
    const float* x  = (const float*)d_in[0];
    const float* h  = (const float*)d_in[1];
    const float* c  = (const float*)d_in[2];
    const float* Wi = (const float*)d_in[3];
    const float* Wh = (const float*)d_in[4];
    const float* bi = (const float*)d_in[5];
    const float* bh = (const float*)d_in[6];
    float* hout = (float*)d_out;
    float* cout = hout + (size_t)BATCH * HID;

    // pass 1: single conversion kernel (xh + weights)
    {
        const size_t n = (size_t)(BATCH + 1024) * KDIM / 8;
        conv_all_kernel<<<(unsigned)((n + 255) / 256), 256>>>(x, h, Wi, Wh);
    }

    // pass 2: GEMM + LSTM. grid: 512 m-tiles x 4 jslices (adjacent bids
    // share A rows -> L2 dedup). 2 CTAs/SM, 16 warps/SM.
    cudaFuncSetAttribute(lstm_gemm_kernel,
                         cudaFuncAttributeMaxDynamicSharedMemorySize, DYN_SMEM);
    lstm_gemm_kernel<<<(BATCH / M_TILE) * 4, 256, DYN_SMEM>>>(c, bi, bh, hout, cout);
}